// round 6
// baseline (speedup 1.0000x reference)
#include <cuda_runtime.h>

// LocalAttn, 2-kernel pipeline for GB300 (sm_103a), round 6.
// Kernel MN: thread=pixel, x[32ci] -> registers (coalesced), conv1 -> fast tanh
//            -> conv2 -> bn -> g_mn [img][ch][px]. No smem staging.
// Kernel F (fused): per (16x16 tile, group, img): compute v = wv@x on the 18x18
//            halo directly from x (registers, L2-hot), into s_v; softmax(mask+nb)
//            from g_mn in registers; combine; write out. No g_v round-trip.

typedef unsigned long long ull;

__device__ float g_mn[2u * 80u * 16384u];        // [img][ch][px]  10.5 MB

__device__ __forceinline__ ull fma2(ull a, ull b, ull c) {
    ull d;
    asm("fma.rn.f32x2 %0, %1, %2, %3;" : "=l"(d) : "l"(a), "l"(b), "l"(c));
    return d;
}
__device__ __forceinline__ float hadd2(ull a) {
    float x, y;
    asm("mov.b64 {%0,%1}, %2;" : "=f"(x), "=f"(y) : "l"(a));
    return x + y;
}
__device__ __forceinline__ ull pk2(float lo, float hi) {
    ull r;
    asm("mov.b64 %0, {%1,%2};" : "=l"(r) : "f"(lo), "f"(hi));
    return r;
}
__device__ __forceinline__ float ftanh(float x) {
    float e = __expf(-2.f * fabsf(x));
    float r = __fdividef(1.f - e, 1.f + e);
    return copysignf(r, x);
}

// ============================ Kernel MN ============================
// grid (64, 8, 2) = (px chunk, conv group, img), block 256, thread = pixel.
__global__ __launch_bounds__(256)
void mn_kernel(
    const float* __restrict__ x,
    const float* __restrict__ w1, const float* __restrict__ b1,
    const float* __restrict__ g1, const float* __restrict__ be1,
    const float* __restrict__ m1, const float* __restrict__ v1,
    const float* __restrict__ w2, const float* __restrict__ b2,
    const float* __restrict__ g2, const float* __restrict__ be2,
    const float* __restrict__ m2, const float* __restrict__ v2)
{
    __shared__ __align__(16) float s_w1g[256];       // w1[g] (8,32)
    __shared__ __align__(16) float s_w2g[80];        // w2[g] (10,8)
    __shared__ float s_a1[8], s_c1[8], s_a2[10], s_c2[10];

    const int t   = threadIdx.x;
    const int px0 = blockIdx.x * 256;
    const int g   = blockIdx.y;
    const int img = blockIdx.z;

    s_w1g[t] = w1[g * 256 + t];
    if (t < 80) s_w2g[t] = w2[g * 80 + t];
    if (t < 8) {
        int ch = g * 8 + t;
        float inv = g1[ch] * rsqrtf(v1[ch] + 1e-5f);
        s_a1[t] = inv;
        s_c1[t] = b1[ch] * inv + be1[ch] - m1[ch] * inv;
    } else if (t >= 32 && t < 42) {
        int o = t - 32, ch = g * 10 + o;
        float inv = g2[ch] * rsqrtf(v2[ch] + 1e-5f);
        s_a2[o] = inv;
        s_c2[o] = b2[ch] * inv + be2[ch] - m2[ch] * inv;
    }

    // x loads: per channel, warp reads 32 consecutive px -> 1 line/request
    const float* xg = x + ((size_t)img * 256 + g * 32) * 16384 + px0 + t;
    float xv[32];
    #pragma unroll
    for (int c = 0; c < 32; c++) xv[c] = __ldg(xg + c * 16384);
    __syncthreads();

    ulonglong2 xr[8];
    #pragma unroll
    for (int q = 0; q < 8; q++) {
        xr[q].x = pk2(xv[4 * q + 0], xv[4 * q + 1]);
        xr[q].y = pk2(xv[4 * q + 2], xv[4 * q + 3]);
    }

    ull acc[8];
    #pragma unroll
    for (int o = 0; o < 8; o++) acc[o] = 0ULL;
    #pragma unroll
    for (int q = 0; q < 8; q++) {
        #pragma unroll
        for (int o = 0; o < 8; o++) {
            ulonglong2 wp = *(const ulonglong2*)(s_w1g + o * 32 + q * 4);
            acc[o] = fma2(xr[q].x, wp.x, acc[o]);
            acc[o] = fma2(xr[q].y, wp.y, acc[o]);
        }
    }
    float tv[8];
    #pragma unroll
    for (int o = 0; o < 8; o++)
        tv[o] = ftanh(hadd2(acc[o]) * s_a1[o] + s_c1[o]);

    float* mb = g_mn + ((size_t)img * 80 + g * 10) * 16384 + px0 + t;
    #pragma unroll
    for (int o2 = 0; o2 < 10; o2++) {
        float a = 0.f;
        #pragma unroll
        for (int o = 0; o < 8; o++) a += tv[o] * s_w2g[o2 * 8 + o];
        mb[(size_t)o2 * 16384] = a * s_a2[o2] + s_c2[o2];
    }
}

// ============================ Kernel F ============================
// grid (8, 8, 16): z = img*8 + g. block 256 (one thread per center pixel).
// dynamic smem: s_v[324*36] + s_wv[1024] = 50752 bytes.
__global__ __launch_bounds__(256, 2)
void fused_kernel(const float* __restrict__ x,
                  const float* __restrict__ wv,
                  float* __restrict__ out)
{
    extern __shared__ __align__(16) float sm[];
    float* s_v  = sm;            // [hp][co] pitch 36
    float* s_wv = sm + 11664;    // wv[g] (32,32)

    const int t   = threadIdx.x;
    const int ty  = t >> 4, tx = t & 15;
    const int w0  = blockIdx.x * 16;
    const int h0  = blockIdx.y * 16;
    const int img = blockIdx.z >> 3;
    const int g   = blockIdx.z & 7;
    const int h   = h0 + ty, w = w0 + tx;
    const int px  = h * 128 + w;

    for (int i = t; i < 1024; i += 256) s_wv[i] = wv[g * 1024 + i];
    __syncthreads();

    // ---- v = wv @ x on the 18x18 halo; x straight to registers (L2-hot) ----
    const float* xg = x + ((size_t)img * 256 + g * 32) * 16384;
    for (int hp = t; hp < 324; hp += 256) {
        int hy = hp / 18, hx = hp - hy * 18;
        int hh = h0 + hy - 1, ww = w0 + hx - 1;
        bool in = ((unsigned)hh < 128u) & ((unsigned)ww < 128u);
        int gpx = hh * 128 + ww;

        float xv[32];
        #pragma unroll
        for (int c = 0; c < 32; c++)
            xv[c] = in ? __ldg(xg + c * 16384 + gpx) : 0.f;

        ulonglong2 xr[8];
        #pragma unroll
        for (int q = 0; q < 8; q++) {
            xr[q].x = pk2(xv[4 * q + 0], xv[4 * q + 1]);
            xr[q].y = pk2(xv[4 * q + 2], xv[4 * q + 3]);
        }

        float* vrow = s_v + hp * 36;
        #pragma unroll
        for (int ch = 0; ch < 4; ch++) {
            ull acc[8];
            #pragma unroll
            for (int o = 0; o < 8; o++) acc[o] = 0ULL;
            #pragma unroll
            for (int q = 0; q < 8; q++) {
                #pragma unroll
                for (int o = 0; o < 8; o++) {
                    ulonglong2 wp = *(const ulonglong2*)(s_wv + (ch * 8 + o) * 32 + q * 4);
                    acc[o] = fma2(xr[q].x, wp.x, acc[o]);
                    acc[o] = fma2(xr[q].y, wp.y, acc[o]);
                }
            }
            float4 r;
            r.x = hadd2(acc[0]); r.y = hadd2(acc[1]);
            r.z = hadd2(acc[2]); r.w = hadd2(acc[3]);
            *(float4*)(vrow + ch * 8) = r;
            r.x = hadd2(acc[4]); r.y = hadd2(acc[5]);
            r.z = hadd2(acc[6]); r.w = hadd2(acc[7]);
            *(float4*)(vrow + ch * 8 + 4) = r;
        }
    }

    // ---- logits: mask (9 strided coalesced) + neighbor (9 predicated) ----
    float a[9];
    {
        const float* nbg   = g_mn + ((size_t)img * 80 + g) * 16384;
        const float* mbase = g_mn + ((size_t)img * 80 + 8 + g * 9) * 16384 + px;
        #pragma unroll
        for (int k = 0; k < 9; k++) {
            int i = k / 3, j = k - i * 3;
            int hh = h + i - 1, ww = w + j - 1;
            float nb = 0.f;
            if (((unsigned)hh < 128u) & ((unsigned)ww < 128u))
                nb = nbg[hh * 128 + ww];
            a[k] = mbase[(size_t)k * 16384] + nb;
        }
        float mx = a[0];
        #pragma unroll
        for (int k = 1; k < 9; k++) mx = fmaxf(mx, a[k]);
        float s = 0.f;
        #pragma unroll
        for (int k = 0; k < 9; k++) { a[k] = __expf(a[k] - mx); s += a[k]; }
        float inv = 1.f / s;
        #pragma unroll
        for (int k = 0; k < 9; k++) a[k] *= inv;
    }
    __syncthreads();

    // ---- combine: out[c] = sum_k a[k] * v[c] at neighbor k ----
    {
        int hpk[9];
        #pragma unroll
        for (int k = 0; k < 9; k++) {
            int i = k / 3, j = k - i * 3;
            hpk[k] = ((ty + i) * 18 + (tx + j)) * 36;
        }
        float* ob = out + ((size_t)img * 256 + g * 32) * 16384 + px;
        #pragma unroll
        for (int c4 = 0; c4 < 8; c4++) {
            float ax = 0.f, ay = 0.f, az = 0.f, aw = 0.f;
            #pragma unroll
            for (int k = 0; k < 9; k++) {
                float4 vv = *(const float4*)(s_v + hpk[k] + c4 * 4);
                ax += a[k] * vv.x; ay += a[k] * vv.y;
                az += a[k] * vv.z; aw += a[k] * vv.w;
            }
            ob[(size_t)(c4 * 4 + 0) * 16384] = ax;
            ob[(size_t)(c4 * 4 + 1) * 16384] = ay;
            ob[(size_t)(c4 * 4 + 2) * 16384] = az;
            ob[(size_t)(c4 * 4 + 3) * 16384] = aw;
        }
    }
}

static const int F_SMEM = (11664 + 1024) * 4;   // 50752 B

extern "C" void kernel_launch(void* const* d_in, const int* in_sizes, int n_in,
                              void* d_out, int out_size) {
    const float* x   = (const float*)d_in[0];
    const float* w1  = (const float*)d_in[1];
    const float* b1  = (const float*)d_in[2];
    const float* g1  = (const float*)d_in[3];
    const float* be1 = (const float*)d_in[4];
    const float* m1  = (const float*)d_in[5];
    const float* v1  = (const float*)d_in[6];
    const float* w2  = (const float*)d_in[7];
    const float* b2  = (const float*)d_in[8];
    const float* g2  = (const float*)d_in[9];
    const float* be2 = (const float*)d_in[10];
    const float* m2  = (const float*)d_in[11];
    const float* v2  = (const float*)d_in[12];
    const float* wv  = (const float*)d_in[13];
    float* out = (float*)d_out;

    static int inited = 0;
    if (!inited) {
        cudaFuncSetAttribute(fused_kernel,
                             cudaFuncAttributeMaxDynamicSharedMemorySize, F_SMEM);
        inited = 1;
    }

    mn_kernel<<<dim3(64, 8, 2), 256>>>(x, w1, b1, g1, be1, m1, v1,
                                       w2, b2, g2, be2, m2, v2);
    fused_kernel<<<dim3(8, 8, 16), 256, F_SMEM>>>(x, wv, out);
}